// round 1
// baseline (speedup 1.0000x reference)
#include <cuda_runtime.h>
#include <cuda_bf16.h>
#include <math.h>

// ---------------------------------------------------------------------------
// Problem constants
// ---------------------------------------------------------------------------
#define NB      256     // batch
#define HH      512     // H
#define KSZ     256     // KS
#define VSZ     256     // VS
#define TT      512     // T (encoder time)
#define TEXTLEN 301
#define MAXLEN  300     // TEXT_LEN - 1
#define VOCAB   35

#define K1TOT   1280    // (H + VS) + H   = 768 + 512
#define K2TOT   768     // H + KS        = 512 + 256
#define ROWS1   2048    // 4*H
#define ROWS2   1024    // 4*KS

// ---------------------------------------------------------------------------
// Device scratch (no cudaMalloc allowed)
// ---------------------------------------------------------------------------
__device__ float g_W1[ROWS1 * K1TOT];   // packed [W_ih1 | W_hh1]
__device__ float g_W2[ROWS2 * K2TOT];   // packed [W_ih2 | W_hh2]
__device__ float g_b1[ROWS1];
__device__ float g_b2[ROWS2];
__device__ float g_h1[2][NB * HH];
__device__ float g_c1[NB * HH];
__device__ float g_h2[2][NB * KSZ];
__device__ float g_c2[NB * KSZ];
__device__ float g_ctx[NB * VSZ];

// ---------------------------------------------------------------------------
// Init: pack weights, sum biases, zero states.  Runs once per kernel_launch.
// ---------------------------------------------------------------------------
__global__ void init_kernel(const float* __restrict__ Wih1, const float* __restrict__ Whh1,
                            const float* __restrict__ bih1, const float* __restrict__ bhh1,
                            const float* __restrict__ Wih2, const float* __restrict__ Whh2,
                            const float* __restrict__ bih2, const float* __restrict__ bhh2)
{
    int idx = blockIdx.x * blockDim.x + threadIdx.x;
    int stride = gridDim.x * blockDim.x;

    for (int i = idx; i < ROWS1 * K1TOT; i += stride) {
        int row = i / K1TOT, k = i - row * K1TOT;
        g_W1[i] = (k < 768) ? Wih1[row * 768 + k] : Whh1[row * 512 + (k - 768)];
    }
    for (int i = idx; i < ROWS2 * K2TOT; i += stride) {
        int row = i / K2TOT, k = i - row * K2TOT;
        g_W2[i] = (k < 512) ? Wih2[row * 512 + k] : Whh2[row * 256 + (k - 512)];
    }
    for (int i = idx; i < ROWS1; i += stride) g_b1[i] = bih1[i] + bhh1[i];
    for (int i = idx; i < ROWS2; i += stride) g_b2[i] = bih2[i] + bhh2[i];

    for (int i = idx; i < NB * HH; i += stride) { g_h1[0][i] = 0.f; g_h1[1][i] = 0.f; g_c1[i] = 0.f; }
    for (int i = idx; i < NB * KSZ; i += stride) {
        g_h2[0][i] = 0.f; g_h2[1][i] = 0.f; g_c2[i] = 0.f; g_ctx[i] = 0.f;
    }
}

__device__ __forceinline__ float sigmoidf_(float x) { return 1.f / (1.f + expf(-x)); }

// ---------------------------------------------------------------------------
// LSTM1: g = [emb(text[:,t]) | ctx | h1] @ W1^T + b1 ; cell update.
// Block tile: 32 batch x 32 hidden x 4 gates. Grid (8, 16). 256 threads.
// ---------------------------------------------------------------------------
__global__ __launch_bounds__(256) void lstm1_kernel(const int* __restrict__ text,
                                                    const float* __restrict__ emb,
                                                    int step, int par)
{
    __shared__ float As[32][33];
    __shared__ float Ws[4][32][33];

    const int nb = blockIdx.x * 32;
    const int jb = blockIdx.y * 32;
    const int tid = threadIdx.x;
    const int tj = tid & 31;        // lane: j index
    const int tw = tid >> 5;        // warp: batch group

    const float* __restrict__ h1p = g_h1[par];
    float* __restrict__ h1n = g_h1[par ^ 1];

    float acc[4][4];
#pragma unroll
    for (int g = 0; g < 4; g++)
#pragma unroll
        for (int r = 0; r < 4; r++) acc[g][r] = 0.f;

    for (int k0 = 0; k0 < K1TOT; k0 += 32) {
        // ---- stage A tile (32 rows x 32 k) ----
#pragma unroll
        for (int r = 0; r < 4; r++) {
            int nn = (tid >> 5) + 8 * r;
            int n  = nb + nn;
            int k  = k0 + (tid & 31);
            float v;
            if (k < 512) {
                int tok = text[n * TEXTLEN + step];
                v = emb[tok * HH + k];
            } else if (k < 768) {
                v = g_ctx[n * VSZ + (k - 512)];
            } else {
                v = h1p[n * HH + (k - 768)];
            }
            As[nn][tid & 31] = v;
        }
        // ---- stage W tile (4 gates x 32 j x 32 k), stored [g][k][j] ----
#pragma unroll
        for (int it = 0; it < 16; it++) {
            int pair = (tid >> 5) + 8 * it;   // 0..127
            int g  = pair >> 5;
            int jj = pair & 31;
            int kk = tid & 31;
            Ws[g][kk][jj] = g_W1[(g * HH + jb + jj) * K1TOT + k0 + kk];
        }
        __syncthreads();
#pragma unroll
        for (int kk = 0; kk < 32; kk++) {
            float a0 = As[tw * 4 + 0][kk];
            float a1 = As[tw * 4 + 1][kk];
            float a2 = As[tw * 4 + 2][kk];
            float a3 = As[tw * 4 + 3][kk];
#pragma unroll
            for (int g = 0; g < 4; g++) {
                float w = Ws[g][kk][tj];
                acc[g][0] = fmaf(a0, w, acc[g][0]);
                acc[g][1] = fmaf(a1, w, acc[g][1]);
                acc[g][2] = fmaf(a2, w, acc[g][2]);
                acc[g][3] = fmaf(a3, w, acc[g][3]);
            }
        }
        __syncthreads();
    }

    const int j = jb + tj;
    const float bi = g_b1[j];
    const float bf = g_b1[HH + j];
    const float bg = g_b1[2 * HH + j];
    const float bo = g_b1[3 * HH + j];
#pragma unroll
    for (int r = 0; r < 4; r++) {
        int n = nb + tw * 4 + r;
        float gi = acc[0][r] + bi;
        float gf = acc[1][r] + bf;
        float gg = acc[2][r] + bg;
        float go = acc[3][r] + bo;
        float c  = sigmoidf_(gf) * g_c1[n * HH + j] + sigmoidf_(gi) * tanhf(gg);
        g_c1[n * HH + j] = c;
        h1n[n * HH + j]  = sigmoidf_(go) * tanhf(c);
    }
}

// ---------------------------------------------------------------------------
// LSTM2: g = [h1_new | h2] @ W2^T + b2 ; cell update. Grid (8, 8). 256 threads.
// ---------------------------------------------------------------------------
__global__ __launch_bounds__(256) void lstm2_kernel(int par)
{
    __shared__ float As[32][33];
    __shared__ float Ws[4][32][33];

    const int nb = blockIdx.x * 32;
    const int jb = blockIdx.y * 32;
    const int tid = threadIdx.x;
    const int tj = tid & 31;
    const int tw = tid >> 5;

    const float* __restrict__ h1n = g_h1[par ^ 1];
    const float* __restrict__ h2p = g_h2[par];
    float* __restrict__ h2n = g_h2[par ^ 1];

    float acc[4][4];
#pragma unroll
    for (int g = 0; g < 4; g++)
#pragma unroll
        for (int r = 0; r < 4; r++) acc[g][r] = 0.f;

    for (int k0 = 0; k0 < K2TOT; k0 += 32) {
#pragma unroll
        for (int r = 0; r < 4; r++) {
            int nn = (tid >> 5) + 8 * r;
            int n  = nb + nn;
            int k  = k0 + (tid & 31);
            float v = (k < 512) ? h1n[n * HH + k] : h2p[n * KSZ + (k - 512)];
            As[nn][tid & 31] = v;
        }
#pragma unroll
        for (int it = 0; it < 16; it++) {
            int pair = (tid >> 5) + 8 * it;
            int g  = pair >> 5;
            int jj = pair & 31;
            int kk = tid & 31;
            Ws[g][kk][jj] = g_W2[(g * KSZ + jb + jj) * K2TOT + k0 + kk];
        }
        __syncthreads();
#pragma unroll
        for (int kk = 0; kk < 32; kk++) {
            float a0 = As[tw * 4 + 0][kk];
            float a1 = As[tw * 4 + 1][kk];
            float a2 = As[tw * 4 + 2][kk];
            float a3 = As[tw * 4 + 3][kk];
#pragma unroll
            for (int g = 0; g < 4; g++) {
                float w = Ws[g][kk][tj];
                acc[g][0] = fmaf(a0, w, acc[g][0]);
                acc[g][1] = fmaf(a1, w, acc[g][1]);
                acc[g][2] = fmaf(a2, w, acc[g][2]);
                acc[g][3] = fmaf(a3, w, acc[g][3]);
            }
        }
        __syncthreads();
    }

    const int j = jb + tj;
    const float bi = g_b2[j];
    const float bf = g_b2[KSZ + j];
    const float bg = g_b2[2 * KSZ + j];
    const float bo = g_b2[3 * KSZ + j];
#pragma unroll
    for (int r = 0; r < 4; r++) {
        int n = nb + tw * 4 + r;
        float gi = acc[0][r] + bi;
        float gf = acc[1][r] + bf;
        float gg = acc[2][r] + bg;
        float go = acc[3][r] + bo;
        float c  = sigmoidf_(gf) * g_c2[n * KSZ + j] + sigmoidf_(gi) * tanhf(gg);
        g_c2[n * KSZ + j] = c;
        h2n[n * KSZ + j]  = sigmoidf_(go) * tanhf(c);
    }
}

// ---------------------------------------------------------------------------
// Attention + output projection. One block per batch row, 256 threads.
// Masked rows (t >= lens//8) are skipped exactly (they softmax to 0).
// ---------------------------------------------------------------------------
__global__ __launch_bounds__(256) void attn_kernel(const float* __restrict__ enc_key,
                                                   const float* __restrict__ enc_values,
                                                   const int* __restrict__ lens,
                                                   const float* __restrict__ W_out,
                                                   const float* __restrict__ b_out,
                                                   float* __restrict__ out,
                                                   int step, int par)
{
    __shared__ float sh_q[KSZ];
    __shared__ float sh_c[VSZ];
    __shared__ float sh_e[TT];
    __shared__ float red[8];

    const int n = blockIdx.x;
    const int tid = threadIdx.x;
    const int lane = tid & 31;
    const int warp = tid >> 5;

    const float* __restrict__ h2 = g_h2[par ^ 1] + n * KSZ;
    sh_q[tid] = h2[tid];
    __syncthreads();

    int nv = lens[n] >> 3;
    if (nv > TT) nv = TT;
    if (nv < 1)  nv = 1;

    const float* __restrict__ Kb = enc_key + (size_t)n * TT * KSZ;
    float lmax = -1e30f;
    for (int t = warp; t < nv; t += 8) {
        const float* kr = Kb + (size_t)t * KSZ;
        float s = 0.f;
#pragma unroll
        for (int i = 0; i < 8; i++) s = fmaf(kr[lane + 32 * i], sh_q[lane + 32 * i], s);
#pragma unroll
        for (int o = 16; o; o >>= 1) s += __shfl_xor_sync(0xffffffffu, s, o);
        if (lane == 0) sh_e[t] = s;
        lmax = fmaxf(lmax, s);
    }
    if (lane == 0) red[warp] = lmax;
    __syncthreads();

    float emax = red[0];
#pragma unroll
    for (int w = 1; w < 8; w++) emax = fmaxf(emax, red[w]);

    float lsum = 0.f;
    for (int t = tid; t < nv; t += 256) {
        float e = expf(sh_e[t] - emax);
        sh_e[t] = e;
        lsum += e;
    }
#pragma unroll
    for (int o = 16; o; o >>= 1) lsum += __shfl_xor_sync(0xffffffffu, lsum, o);
    __syncthreads();
    if (lane == 0) red[warp] = lsum;
    __syncthreads();

    float tot = red[0];
#pragma unroll
    for (int w = 1; w < 8; w++) tot += red[w];
    float inv = 1.f / tot;

    // context: thread == value-dim k
    const float* __restrict__ Vb = enc_values + (size_t)n * TT * VSZ;
    float a0 = 0.f, a1 = 0.f, a2 = 0.f, a3 = 0.f;
    int t = 0;
    for (; t + 4 <= nv; t += 4) {
        a0 = fmaf(sh_e[t + 0], Vb[(size_t)(t + 0) * VSZ + tid], a0);
        a1 = fmaf(sh_e[t + 1], Vb[(size_t)(t + 1) * VSZ + tid], a1);
        a2 = fmaf(sh_e[t + 2], Vb[(size_t)(t + 2) * VSZ + tid], a2);
        a3 = fmaf(sh_e[t + 3], Vb[(size_t)(t + 3) * VSZ + tid], a3);
    }
    for (; t < nv; t++) a0 = fmaf(sh_e[t], Vb[(size_t)t * VSZ + tid], a0);
    float ctx = (a0 + a1 + a2 + a3) * inv;
    sh_c[tid] = ctx;
    g_ctx[n * VSZ + tid] = ctx;
    __syncthreads();

    // pred = [h2 | ctx] @ W_out^T + b_out
    for (int v = warp; v < VOCAB; v += 8) {
        float s = 0.f;
#pragma unroll
        for (int i = lane; i < KSZ + VSZ; i += 32) {
            float f = (i < KSZ) ? sh_q[i] : sh_c[i - KSZ];
            s = fmaf(f, W_out[v * (KSZ + VSZ) + i], s);
        }
#pragma unroll
        for (int o = 16; o; o >>= 1) s += __shfl_xor_sync(0xffffffffu, s, o);
        if (lane == 0) out[((size_t)n * MAXLEN + step) * VOCAB + v] = s + b_out[v];
    }
}

// ---------------------------------------------------------------------------
// Launch: init + 300 x (lstm1, lstm2, attn).  All plain default-stream
// launches -> graph-capturable, allocation-free.
// ---------------------------------------------------------------------------
extern "C" void kernel_launch(void* const* d_in, const int* in_sizes, int n_in,
                              void* d_out, int out_size)
{
    const float* enc_key    = (const float*)d_in[0];
    const float* enc_values = (const float*)d_in[1];
    const int*   text       = (const int*)  d_in[2];
    const int*   lens       = (const int*)  d_in[3];
    // d_in[4] = teach (unused; teacher forcing always on in reference)
    const float* emb        = (const float*)d_in[5];
    const float* W_ih1      = (const float*)d_in[6];
    const float* W_hh1      = (const float*)d_in[7];
    const float* b_ih1      = (const float*)d_in[8];
    const float* b_hh1      = (const float*)d_in[9];
    const float* W_ih2      = (const float*)d_in[10];
    const float* W_hh2      = (const float*)d_in[11];
    const float* b_ih2      = (const float*)d_in[12];
    const float* b_hh2      = (const float*)d_in[13];
    const float* W_out      = (const float*)d_in[14];
    const float* b_out      = (const float*)d_in[15];
    float* out = (float*)d_out;

    init_kernel<<<1024, 256>>>(W_ih1, W_hh1, b_ih1, b_hh1, W_ih2, W_hh2, b_ih2, b_hh2);

    for (int t = 0; t < MAXLEN; t++) {
        int par = t & 1;
        lstm1_kernel<<<dim3(8, 16), 256>>>(text, emb, t, par);
        lstm2_kernel<<<dim3(8, 8), 256>>>(par);
        attn_kernel<<<NB, 256>>>(enc_key, enc_values, lens, W_out, b_out, out, t, par);
    }
}

// round 5
// speedup vs baseline: 2.6741x; 2.6741x over previous
#include <cuda_runtime.h>
#include <cuda_bf16.h>
#include <math.h>

// ---------------------------------------------------------------------------
// Problem constants
// ---------------------------------------------------------------------------
#define NB      256
#define HH      512
#define KSZ     256
#define VSZ     256
#define TT      512
#define TEXTLEN 301
#define MAXLEN  300
#define VOCAB   35

#define K1      768     // ctx(256) + h1(512)   (emb part folded into table)
#define K2      768     // h1(512) + h2(256)
#define R1      2048    // 4*H   rows, packed r = h*4 + gate
#define R2      1024    // 4*KS  rows, packed r = h*4 + gate

// ---------------------------------------------------------------------------
// Device scratch
// ---------------------------------------------------------------------------
__device__ float g_W1T[K1 * R1];          // [k][r] transposed, gate-interleaved
__device__ float g_W2T[K2 * R2];
__device__ float g_embB[VOCAB * R1];      // emb@W_ih1[:, :512]^T + b_ih1 + b_hh1
__device__ float g_b2p[R2];               // b_ih2 + b_hh2, packed order
__device__ float g_h1[2][NB * HH];
__device__ float g_c1[NB * HH];
__device__ float g_h2[2][NB * KSZ];
__device__ float g_c2[NB * KSZ];
__device__ float g_ctx[NB * VSZ];
__device__ int g_nv[NB];
__device__ int g_order[NB];

__device__ __forceinline__ float sigmoidf_(float x) { return 1.f / (1.f + expf(-x)); }

// ---------------------------------------------------------------------------
// Init 1: weight transposes (gate-interleaved), packed bias, states, nv.
// ---------------------------------------------------------------------------
__global__ void init_misc(const float* __restrict__ Wih1, const float* __restrict__ Whh1,
                          const float* __restrict__ Wih2, const float* __restrict__ Whh2,
                          const float* __restrict__ bih2, const float* __restrict__ bhh2,
                          const int* __restrict__ lens)
{
    int idx = blockIdx.x * blockDim.x + threadIdx.x;
    int stride = gridDim.x * blockDim.x;

    for (int i = idx; i < K1 * R1; i += stride) {
        int k = i >> 11, r = i & (R1 - 1);
        int h = r >> 2, g = r & 3, ro = g * 512 + h;
        g_W1T[i] = (k < 256) ? Wih1[ro * 768 + 512 + k]       // ctx columns
                             : Whh1[ro * 512 + (k - 256)];    // h1 columns
    }
    for (int i = idx; i < K2 * R2; i += stride) {
        int k = i >> 10, r = i & (R2 - 1);
        int h = r >> 2, g = r & 3, ro = g * 256 + h;
        g_W2T[i] = (k < 512) ? Wih2[ro * 512 + k]
                             : Whh2[ro * 256 + (k - 512)];
    }
    for (int r = idx; r < R2; r += stride) {
        int h = r >> 2, g = r & 3, ro = g * 256 + h;
        g_b2p[r] = bih2[ro] + bhh2[ro];
    }
    for (int i = idx; i < NB * HH; i += stride) {
        g_h1[0][i] = 0.f; g_h1[1][i] = 0.f; g_c1[i] = 0.f;
    }
    for (int i = idx; i < NB * KSZ; i += stride) {
        g_h2[0][i] = 0.f; g_h2[1][i] = 0.f; g_c2[i] = 0.f; g_ctx[i] = 0.f;
    }
    for (int n = idx; n < NB; n += stride) {
        int v = lens[n] >> 3;
        if (v < 1)  v = 1;
        if (v > TT) v = TT;
        g_nv[n] = v;
    }
}

// ---------------------------------------------------------------------------
// Init 2: per-vocab precomputed gate base: emb[v] @ W_ih1[:, :512]^T + biases.
// Grid (VOCAB, 8), 256 threads.
// ---------------------------------------------------------------------------
__global__ void embB_kernel(const float* __restrict__ emb, const float* __restrict__ Wih1,
                            const float* __restrict__ bih1, const float* __restrict__ bhh1)
{
    __shared__ float se[512];
    int v = blockIdx.x;
    int tid = threadIdx.x;
    se[tid]       = emb[v * HH + tid];
    se[tid + 256] = emb[v * HH + tid + 256];
    __syncthreads();
    int r = blockIdx.y * 256 + tid;
    int h = r >> 2, g = r & 3, ro = g * 512 + h;
    float acc = bih1[ro] + bhh1[ro];
    const float* __restrict__ wr = Wih1 + (size_t)ro * 768;
#pragma unroll 8
    for (int k = 0; k < 512; k++) acc = fmaf(se[k], wr[k], acc);
    g_embB[v * R1 + r] = acc;
}

// ---------------------------------------------------------------------------
// Init 3: sort batch rows by nv desc (scheduling order for attn tail).
// ---------------------------------------------------------------------------
__global__ void sort_kernel()
{
    __shared__ int snv[NB];
    int tid = threadIdx.x;
    snv[tid] = g_nv[tid];
    __syncthreads();
    int my = snv[tid];
    int rank = 0;
    for (int m = 0; m < NB; m++)
        rank += (snv[m] > my) || (snv[m] == my && m < tid);
    g_order[rank] = tid;
}

// ---------------------------------------------------------------------------
// LSTM1: gates = [ctx | h1] @ W1T + embB[tok];  cell update.
// Tile 64 rows x 32 batch, 256 threads, thread tile 4(gates of one h) x 2 n.
// Grid (32, 8) = 256 blocks.
// ---------------------------------------------------------------------------
__global__ __launch_bounds__(256) void lstm1_kernel(const int* __restrict__ text,
                                                    int step, int par)
{
    __shared__ float Ws[32][64];
    __shared__ float As[32][34];

    const int tid = threadIdx.x;
    const int tx = tid & 15;          // h within tile
    const int ty = tid >> 4;          // n-pair
    const int rb = blockIdx.x * 64;
    const int nb = blockIdx.y * 32;

    const float* __restrict__ h1p = g_h1[par];
    float* __restrict__ h1n = g_h1[par ^ 1];

    float acc00 = 0.f, acc01 = 0.f, acc10 = 0.f, acc11 = 0.f;
    float acc20 = 0.f, acc21 = 0.f, acc30 = 0.f, acc31 = 0.f;

    for (int k0 = 0; k0 < K1; k0 += 32) {
        // stage W tile: 32k x 64r = 512 float4, 2 per thread
#pragma unroll
        for (int i = 0; i < 2; i++) {
            int f = tid + i * 256;
            int k = f >> 4, c4 = f & 15;
            *(float4*)&Ws[k][c4 * 4] =
                *(const float4*)&g_W1T[(size_t)(k0 + k) * R1 + rb + c4 * 4];
        }
        // stage A tile: 32k x 32n, transposed
#pragma unroll
        for (int i = 0; i < 4; i++) {
            int nl = (tid >> 5) + i * 8;
            int kk = tid & 31;
            int k = k0 + kk;
            int n = nb + nl;
            As[kk][nl] = (k < 256) ? g_ctx[n * VSZ + k] : h1p[n * HH + (k - 256)];
        }
        __syncthreads();
#pragma unroll
        for (int k = 0; k < 32; k++) {
            float4 w = *(float4*)&Ws[k][tx * 4];
            float2 a = *(float2*)&As[k][ty * 2];
            acc00 = fmaf(w.x, a.x, acc00); acc01 = fmaf(w.x, a.y, acc01);
            acc10 = fmaf(w.y, a.x, acc10); acc11 = fmaf(w.y, a.y, acc11);
            acc20 = fmaf(w.z, a.x, acc20); acc21 = fmaf(w.z, a.y, acc21);
            acc30 = fmaf(w.w, a.x, acc30); acc31 = fmaf(w.w, a.y, acc31);
        }
        __syncthreads();
    }

    const int h = (rb >> 2) + tx;
    float gI[2] = {acc00, acc01};
    float gF[2] = {acc10, acc11};
    float gG[2] = {acc20, acc21};
    float gO[2] = {acc30, acc31};
#pragma unroll
    for (int j = 0; j < 2; j++) {
        int n = nb + ty * 2 + j;
        int tok = text[n * TEXTLEN + step];
        const float* __restrict__ eb = g_embB + tok * R1 + rb + tx * 4;
        float gi = gI[j] + eb[0];
        float gf = gF[j] + eb[1];
        float gg = gG[j] + eb[2];
        float go = gO[j] + eb[3];
        float c = sigmoidf_(gf) * g_c1[n * HH + h] + sigmoidf_(gi) * tanhf(gg);
        g_c1[n * HH + h] = c;
        h1n[n * HH + h] = sigmoidf_(go) * tanhf(c);
    }
}

// ---------------------------------------------------------------------------
// LSTM2: gates = [h1_new | h2] @ W2T + b2p;  cell update.
// Tile 32 rows x 32 batch, 128 threads, thread tile 4 x 2. Grid (32, 8).
// ---------------------------------------------------------------------------
__global__ __launch_bounds__(128) void lstm2_kernel(int par)
{
    __shared__ float Ws[32][32];
    __shared__ float As[32][34];

    const int tid = threadIdx.x;
    const int tx = tid & 7;
    const int ty = tid >> 3;          // 0..15
    const int rb = blockIdx.x * 32;
    const int nb = blockIdx.y * 32;

    const float* __restrict__ h1n = g_h1[par ^ 1];
    const float* __restrict__ h2p = g_h2[par];
    float* __restrict__ h2n = g_h2[par ^ 1];

    float acc00 = 0.f, acc01 = 0.f, acc10 = 0.f, acc11 = 0.f;
    float acc20 = 0.f, acc21 = 0.f, acc30 = 0.f, acc31 = 0.f;

    for (int k0 = 0; k0 < K2; k0 += 32) {
        // stage W: 32k x 32r = 256 float4, 2 per thread
#pragma unroll
        for (int i = 0; i < 2; i++) {
            int f = tid + i * 128;
            int k = f >> 3, c4 = f & 7;
            *(float4*)&Ws[k][c4 * 4] =
                *(const float4*)&g_W2T[(size_t)(k0 + k) * R2 + rb + c4 * 4];
        }
        // stage A: 32k x 32n
#pragma unroll
        for (int i = 0; i < 8; i++) {
            int nl = (tid >> 5) + i * 4;
            int kk = tid & 31;
            int k = k0 + kk;
            int n = nb + nl;
            As[kk][nl] = (k < 512) ? h1n[n * HH + k] : h2p[n * KSZ + (k - 512)];
        }
        __syncthreads();
#pragma unroll
        for (int k = 0; k < 32; k++) {
            float4 w = *(float4*)&Ws[k][tx * 4];
            float2 a = *(float2*)&As[k][ty * 2];
            acc00 = fmaf(w.x, a.x, acc00); acc01 = fmaf(w.x, a.y, acc01);
            acc10 = fmaf(w.y, a.x, acc10); acc11 = fmaf(w.y, a.y, acc11);
            acc20 = fmaf(w.z, a.x, acc20); acc21 = fmaf(w.z, a.y, acc21);
            acc30 = fmaf(w.w, a.x, acc30); acc31 = fmaf(w.w, a.y, acc31);
        }
        __syncthreads();
    }

    const int h = (rb >> 2) + tx;
    const int r4 = rb + tx * 4;
    const float bi = g_b2p[r4 + 0];
    const float bf = g_b2p[r4 + 1];
    const float bg = g_b2p[r4 + 2];
    const float bo = g_b2p[r4 + 3];
    float gI[2] = {acc00, acc01};
    float gF[2] = {acc10, acc11};
    float gG[2] = {acc20, acc21};
    float gO[2] = {acc30, acc31};
#pragma unroll
    for (int j = 0; j < 2; j++) {
        int n = nb + ty * 2 + j;
        float gi = gI[j] + bi;
        float gf = gF[j] + bf;
        float gg = gG[j] + bg;
        float go = gO[j] + bo;
        float c = sigmoidf_(gf) * g_c2[n * KSZ + h] + sigmoidf_(gi) * tanhf(gg);
        g_c2[n * KSZ + h] = c;
        h2n[n * KSZ + h] = sigmoidf_(go) * tanhf(c);
    }
}

// ---------------------------------------------------------------------------
// Attention + output projection, fp32 K/V, high-MLP.
// One block per batch row (length-sorted order), 512 threads / 16 warps.
// Warp handles row t; each lane covers 8 dims (2x LDG.128); 4-way t-unroll.
// ---------------------------------------------------------------------------
__global__ __launch_bounds__(512) void attn_kernel(const float* __restrict__ enc_key,
                                                   const float* __restrict__ enc_values,
                                                   const float* __restrict__ W_out,
                                                   const float* __restrict__ b_out,
                                                   float* __restrict__ out,
                                                   int step, int par)
{
    __shared__ float sh_q[KSZ];
    __shared__ float sh_c[VSZ];
    __shared__ float sh_e[TT];
    __shared__ float sh_red[16];
    __shared__ float sh_inv;
    __shared__ float sh_acc[16][VSZ];

    const int tid = threadIdx.x;
    const int lane = tid & 31;
    const int warp = tid >> 5;
    const int n = g_order[blockIdx.x];
    const int nv = g_nv[n];

    if (tid < KSZ) sh_q[tid] = g_h2[par ^ 1][n * KSZ + tid];
    __syncthreads();

    // each lane owns dims [lane*8, lane*8+8)
    float qr[8];
#pragma unroll
    for (int i = 0; i < 8; i++) qr[i] = sh_q[lane * 8 + i];

    // ---- energies ----
    const float* __restrict__ Kb = enc_key + (size_t)n * TT * KSZ;
    float lmax = -1e30f;
    for (int c = 0; c < nv; c += 64) {
        float4 ka[4], kb[4];
        bool act[4];
#pragma unroll
        for (int u = 0; u < 4; u++) {
            int t = c + warp + 16 * u;
            act[u] = (t < nv);
            if (act[u]) {
                const float* kr = Kb + (size_t)t * KSZ + lane * 8;
                ka[u] = *(const float4*)kr;
                kb[u] = *(const float4*)(kr + 4);
            }
        }
#pragma unroll
        for (int u = 0; u < 4; u++) {
            if (act[u]) {
                float s = qr[0] * ka[u].x + qr[1] * ka[u].y + qr[2] * ka[u].z + qr[3] * ka[u].w
                        + qr[4] * kb[u].x + qr[5] * kb[u].y + qr[6] * kb[u].z + qr[7] * kb[u].w;
#pragma unroll
                for (int o = 16; o; o >>= 1) s += __shfl_xor_sync(0xffffffffu, s, o);
                if (lane == 0) sh_e[c + warp + 16 * u] = s;
                lmax = fmaxf(lmax, s);
            }
        }
    }
    if (lane == 0) sh_red[warp] = lmax;
    __syncthreads();

    float emax = sh_red[0];
#pragma unroll
    for (int w = 1; w < 16; w++) emax = fmaxf(emax, sh_red[w]);

    // ---- softmax (unnormalized) ----
    float lsum = 0.f;
    for (int t = tid; t < nv; t += 512) {
        float e = expf(sh_e[t] - emax);
        sh_e[t] = e;
        lsum += e;
    }
#pragma unroll
    for (int o = 16; o; o >>= 1) lsum += __shfl_xor_sync(0xffffffffu, lsum, o);
    __syncthreads();
    if (lane == 0) sh_red[warp] = lsum;
    __syncthreads();
    if (tid == 0) {
        float tot = 0.f;
#pragma unroll
        for (int w = 0; w < 16; w++) tot += sh_red[w];
        sh_inv = 1.f / tot;
    }
    __syncthreads();
    const float inv = sh_inv;

    // ---- context ----
    const float* __restrict__ Vb = enc_values + (size_t)n * TT * VSZ;
    float acc[8];
#pragma unroll
    for (int i = 0; i < 8; i++) acc[i] = 0.f;
    for (int c = 0; c < nv; c += 64) {
        float4 va[4], vb[4];
        float ew[4];
        bool act[4];
#pragma unroll
        for (int u = 0; u < 4; u++) {
            int t = c + warp + 16 * u;
            act[u] = (t < nv);
            if (act[u]) {
                const float* vr = Vb + (size_t)t * VSZ + lane * 8;
                va[u] = *(const float4*)vr;
                vb[u] = *(const float4*)(vr + 4);
                ew[u] = sh_e[t];
            }
        }
#pragma unroll
        for (int u = 0; u < 4; u++) {
            if (act[u]) {
                float e = ew[u];
                acc[0] = fmaf(e, va[u].x, acc[0]); acc[1] = fmaf(e, va[u].y, acc[1]);
                acc[2] = fmaf(e, va[u].z, acc[2]); acc[3] = fmaf(e, va[u].w, acc[3]);
                acc[4] = fmaf(e, vb[u].x, acc[4]); acc[5] = fmaf(e, vb[u].y, acc[5]);
                acc[6] = fmaf(e, vb[u].z, acc[6]); acc[7] = fmaf(e, vb[u].w, acc[7]);
            }
        }
    }
#pragma unroll
    for (int i = 0; i < 8; i++) sh_acc[warp][lane * 8 + i] = acc[i];
    __syncthreads();

    if (tid < VSZ) {
        float ctx = 0.f;
#pragma unroll
        for (int w = 0; w < 16; w++) ctx += sh_acc[w][tid];
        ctx *= inv;
        sh_c[tid] = ctx;
        g_ctx[n * VSZ + tid] = ctx;
    }
    __syncthreads();

    // ---- output projection: pred = [h2 | ctx] @ W_out^T + b_out ----
    for (int v = warp; v < VOCAB; v += 16) {
        float s = 0.f;
        const float* __restrict__ wr = W_out + v * (KSZ + VSZ);
#pragma unroll
        for (int i = lane; i < KSZ + VSZ; i += 32) {
            float f = (i < KSZ) ? sh_q[i] : sh_c[i - KSZ];
            s = fmaf(f, wr[i], s);
        }
#pragma unroll
        for (int o = 16; o; o >>= 1) s += __shfl_xor_sync(0xffffffffu, s, o);
        if (lane == 0) out[((size_t)n * MAXLEN + step) * VOCAB + v] = s + b_out[v];
    }
}

// ---------------------------------------------------------------------------
// kernel_launch: init (3 kernels) + 300 x (lstm1, lstm2, attn)
// ---------------------------------------------------------------------------
extern "C" void kernel_launch(void* const* d_in, const int* in_sizes, int n_in,
                              void* d_out, int out_size)
{
    const float* enc_key    = (const float*)d_in[0];
    const float* enc_values = (const float*)d_in[1];
    const int*   text       = (const int*)  d_in[2];
    const int*   lens       = (const int*)  d_in[3];
    const float* emb        = (const float*)d_in[5];
    const float* W_ih1      = (const float*)d_in[6];
    const float* W_hh1      = (const float*)d_in[7];
    const float* b_ih1      = (const float*)d_in[8];
    const float* b_hh1      = (const float*)d_in[9];
    const float* W_ih2      = (const float*)d_in[10];
    const float* W_hh2      = (const float*)d_in[11];
    const float* b_ih2      = (const float*)d_in[12];
    const float* b_hh2      = (const float*)d_in[13];
    const float* W_out      = (const float*)d_in[14];
    const float* b_out      = (const float*)d_in[15];
    float* out = (float*)d_out;

    init_misc<<<1024, 256>>>(W_ih1, W_hh1, W_ih2, W_hh2, b_ih2, b_hh2, lens);
    embB_kernel<<<dim3(VOCAB, 8), 256>>>(emb, W_ih1, b_ih1, b_hh1);
    sort_kernel<<<1, 256>>>();

    for (int t = 0; t < MAXLEN; t++) {
        int par = t & 1;
        lstm1_kernel<<<dim3(32, 8), 256>>>(text, t, par);
        lstm2_kernel<<<dim3(32, 8), 128>>>(par);
        attn_kernel<<<NB, 512>>>(enc_key, enc_values, W_out, b_out, out, t, par);
    }
}

// round 7
// speedup vs baseline: 3.0753x; 1.1500x over previous
#include <cuda_runtime.h>
#include <cuda_bf16.h>
#include <math.h>

// ---------------------------------------------------------------------------
// Problem constants
// ---------------------------------------------------------------------------
#define NB      256
#define HH      512
#define KSZ     256
#define VSZ     256
#define TT      512
#define TEXTLEN 301
#define MAXLEN  300
#define VOCAB   35

#define K1      768     // ctx(256) + h1(512)   (emb part folded into table)
#define K2      768     // h1(512) + h2(256)
#define R1      2048    // 4*H   rows, packed r = h*4 + gate
#define R2      1024    // 4*KS  rows, packed r = h*4 + gate

// ---------------------------------------------------------------------------
// Device scratch
// ---------------------------------------------------------------------------
__device__ float g_W1T[K1 * R1];          // [k][r] transposed, gate-interleaved
__device__ float g_W2T[K2 * R2];
__device__ float g_embB[VOCAB * R1];      // emb@W_ih1[:, :512]^T + b_ih1 + b_hh1
__device__ float g_b2p[R2];               // b_ih2 + b_hh2, packed order
__device__ float g_h1[2][NB * HH];
__device__ float g_c1[NB * HH];
__device__ float g_h2[2][NB * KSZ];
__device__ float g_c2[NB * KSZ];
__device__ float g_ctx[NB * VSZ];
__device__ int g_nv[NB];
__device__ int g_order[NB];

__device__ __forceinline__ float sigmoidf_(float x) { return 1.f / (1.f + expf(-x)); }

// ---------------------------------------------------------------------------
// Init 1: weight transposes (gate-interleaved), packed bias, states, nv.
// ---------------------------------------------------------------------------
__global__ void init_misc(const float* __restrict__ Wih1, const float* __restrict__ Whh1,
                          const float* __restrict__ Wih2, const float* __restrict__ Whh2,
                          const float* __restrict__ bih2, const float* __restrict__ bhh2,
                          const int* __restrict__ lens)
{
    int idx = blockIdx.x * blockDim.x + threadIdx.x;
    int stride = gridDim.x * blockDim.x;

    for (int i = idx; i < K1 * R1; i += stride) {
        int k = i >> 11, r = i & (R1 - 1);
        int h = r >> 2, g = r & 3, ro = g * 512 + h;
        g_W1T[i] = (k < 256) ? Wih1[ro * 768 + 512 + k]       // ctx columns
                             : Whh1[ro * 512 + (k - 256)];    // h1 columns
    }
    for (int i = idx; i < K2 * R2; i += stride) {
        int k = i >> 10, r = i & (R2 - 1);
        int h = r >> 2, g = r & 3, ro = g * 256 + h;
        g_W2T[i] = (k < 512) ? Wih2[ro * 512 + k]
                             : Whh2[ro * 256 + (k - 512)];
    }
    for (int r = idx; r < R2; r += stride) {
        int h = r >> 2, g = r & 3, ro = g * 256 + h;
        g_b2p[r] = bih2[ro] + bhh2[ro];
    }
    for (int i = idx; i < NB * HH; i += stride) {
        g_h1[0][i] = 0.f; g_h1[1][i] = 0.f; g_c1[i] = 0.f;
    }
    for (int i = idx; i < NB * KSZ; i += stride) {
        g_h2[0][i] = 0.f; g_h2[1][i] = 0.f; g_c2[i] = 0.f; g_ctx[i] = 0.f;
    }
    for (int n = idx; n < NB; n += stride) {
        int v = lens[n] >> 3;
        if (v < 1)  v = 1;
        if (v > TT) v = TT;
        g_nv[n] = v;
    }
}

// ---------------------------------------------------------------------------
// Init 2: per-vocab precomputed gate base: emb[v] @ W_ih1[:, :512]^T + biases.
// Grid (VOCAB, 8), 256 threads.
// ---------------------------------------------------------------------------
__global__ void embB_kernel(const float* __restrict__ emb, const float* __restrict__ Wih1,
                            const float* __restrict__ bih1, const float* __restrict__ bhh1)
{
    __shared__ float se[512];
    int v = blockIdx.x;
    int tid = threadIdx.x;
    se[tid]       = emb[v * HH + tid];
    se[tid + 256] = emb[v * HH + tid + 256];
    __syncthreads();
    int r = blockIdx.y * 256 + tid;
    int h = r >> 2, g = r & 3, ro = g * 512 + h;
    float acc = bih1[ro] + bhh1[ro];
    const float* __restrict__ wr = Wih1 + (size_t)ro * 768;
#pragma unroll 8
    for (int k = 0; k < 512; k++) acc = fmaf(se[k], wr[k], acc);
    g_embB[v * R1 + r] = acc;
}

// ---------------------------------------------------------------------------
// Init 3: sort batch rows by nv desc (scheduling order for attn tail).
// ---------------------------------------------------------------------------
__global__ void sort_kernel()
{
    __shared__ int snv[NB];
    int tid = threadIdx.x;
    snv[tid] = g_nv[tid];
    __syncthreads();
    int my = snv[tid];
    int rank = 0;
    for (int m = 0; m < NB; m++)
        rank += (snv[m] > my) || (snv[m] == my && m < tid);
    g_order[rank] = tid;
}

// ---------------------------------------------------------------------------
// LSTM1: gates = [ctx | h1] @ W1T + embB[tok];  cell update.
// Tile 64 rows x 64 batch, 256 threads, thread tile 4r x 4n (16 acc).
// Double-buffered smem staging (reg prefetch), ONE sync per 32-k chunk.
// Grid (32, 4) = 128 blocks.
// ---------------------------------------------------------------------------
#define L1_NC   (K1 / 32)     // 24 chunks
#define AS1_STR 68            // >=64 cols; 68*4B = 272B = 17*16B (float4-aligned rows)

__global__ __launch_bounds__(256) void lstm1_kernel(const int* __restrict__ text,
                                                    int step, int par)
{
    __shared__ float Ws[2][32][64];
    __shared__ float As[2][32][AS1_STR];

    const int tid = threadIdx.x;
    const int tx = tid & 15;          // r-group: rows rb + tx*4 .. +3
    const int ty = tid >> 4;          // n-group: cols nb + ty*4 .. +3
    const int rb = blockIdx.x * 64;
    const int nb = blockIdx.y * 64;

    const float* __restrict__ h1p = g_h1[par];
    float* __restrict__ h1n = g_h1[par ^ 1];

    // staging thread mapping
    const int wk = tid >> 4;          // W: k rows wk, wk+16 ; col c4*4
    const int wc4 = tid & 15;
    const int an = tid >> 2;          // A: batch row nb+an  (0..63)
    const int ak = tid & 3;           // A: k offsets ak + 4j

    float acc[4][4];
#pragma unroll
    for (int i = 0; i < 4; i++)
#pragma unroll
        for (int j = 0; j < 4; j++) acc[i][j] = 0.f;

    float4 wreg0, wreg1;
    float areg[8];

    // ---- prologue: load + store chunk 0 ----
    {
        const int k0 = 0;
        wreg0 = *(const float4*)&g_W1T[(size_t)(k0 + wk) * R1 + rb + wc4 * 4];
        wreg1 = *(const float4*)&g_W1T[(size_t)(k0 + wk + 16) * R1 + rb + wc4 * 4];
        const float* abase = g_ctx + (size_t)(nb + an) * VSZ + (k0 + ak);
#pragma unroll
        for (int j = 0; j < 8; j++) areg[j] = abase[4 * j];
        *(float4*)&Ws[0][wk][wc4 * 4]      = wreg0;
        *(float4*)&Ws[0][wk + 16][wc4 * 4] = wreg1;
#pragma unroll
        for (int j = 0; j < 8; j++) As[0][ak + 4 * j][an] = areg[j];
    }
    __syncthreads();

#pragma unroll 1
    for (int c = 0; c < L1_NC; c++) {
        // prefetch chunk c+1 into registers
        if (c + 1 < L1_NC) {
            const int k0 = (c + 1) * 32;
            wreg0 = *(const float4*)&g_W1T[(size_t)(k0 + wk) * R1 + rb + wc4 * 4];
            wreg1 = *(const float4*)&g_W1T[(size_t)(k0 + wk + 16) * R1 + rb + wc4 * 4];
            const float* abase = (k0 < 256)
                ? g_ctx + (size_t)(nb + an) * VSZ + (k0 + ak)
                : h1p   + (size_t)(nb + an) * HH  + (k0 - 256 + ak);
#pragma unroll
            for (int j = 0; j < 8; j++) areg[j] = abase[4 * j];
        }
        // compute current buffer
        const int buf = c & 1;
#pragma unroll
        for (int k = 0; k < 32; k++) {
            float4 w = *(float4*)&Ws[buf][k][tx * 4];
            float4 a = *(float4*)&As[buf][k][ty * 4];
            acc[0][0] = fmaf(w.x, a.x, acc[0][0]); acc[0][1] = fmaf(w.x, a.y, acc[0][1]);
            acc[0][2] = fmaf(w.x, a.z, acc[0][2]); acc[0][3] = fmaf(w.x, a.w, acc[0][3]);
            acc[1][0] = fmaf(w.y, a.x, acc[1][0]); acc[1][1] = fmaf(w.y, a.y, acc[1][1]);
            acc[1][2] = fmaf(w.y, a.z, acc[1][2]); acc[1][3] = fmaf(w.y, a.w, acc[1][3]);
            acc[2][0] = fmaf(w.z, a.x, acc[2][0]); acc[2][1] = fmaf(w.z, a.y, acc[2][1]);
            acc[2][2] = fmaf(w.z, a.z, acc[2][2]); acc[2][3] = fmaf(w.z, a.w, acc[2][3]);
            acc[3][0] = fmaf(w.w, a.x, acc[3][0]); acc[3][1] = fmaf(w.w, a.y, acc[3][1]);
            acc[3][2] = fmaf(w.w, a.z, acc[3][2]); acc[3][3] = fmaf(w.w, a.w, acc[3][3]);
        }
        // store prefetched chunk into alternate buffer
        if (c + 1 < L1_NC) {
            const int nbuf = buf ^ 1;
            *(float4*)&Ws[nbuf][wk][wc4 * 4]      = wreg0;
            *(float4*)&Ws[nbuf][wk + 16][wc4 * 4] = wreg1;
#pragma unroll
            for (int j = 0; j < 8; j++) As[nbuf][ak + 4 * j][an] = areg[j];
            __syncthreads();
        }
    }

    // ---- epilogue: add embB[tok], cell update ----
    const int h = (rb >> 2) + tx;          // hidden index (4 gates per h)
#pragma unroll
    for (int j = 0; j < 4; j++) {
        int n = nb + ty * 4 + j;
        int tok = __ldg(&text[n * TEXTLEN + step]);
        float4 eb = *(const float4*)&g_embB[tok * R1 + rb + tx * 4];
        float gi = acc[0][j] + eb.x;
        float gf = acc[1][j] + eb.y;
        float gg = acc[2][j] + eb.z;
        float go = acc[3][j] + eb.w;
        float c = sigmoidf_(gf) * g_c1[n * HH + h] + sigmoidf_(gi) * tanhf(gg);
        g_c1[n * HH + h] = c;
        h1n[n * HH + h] = sigmoidf_(go) * tanhf(c);
    }
}

// ---------------------------------------------------------------------------
// LSTM2: gates = [h1_new | h2] @ W2T + b2p;  cell update.
// Tile 64 rows x 32 batch, 256 threads, thread tile 4r x 2n.
// Double-buffered, one sync per chunk. Grid (16, 8) = 128 blocks.
// ---------------------------------------------------------------------------
#define L2_NC   (K2 / 32)     // 24 chunks
#define AS2_STR 34

__global__ __launch_bounds__(256) void lstm2_kernel(int par)
{
    __shared__ float Ws[2][32][64];
    __shared__ float As[2][32][AS2_STR];

    const int tid = threadIdx.x;
    const int tx = tid & 15;          // r-group
    const int ty = tid >> 4;          // n-pair: cols nb + ty*2, +1
    const int rb = blockIdx.x * 64;
    const int nb = blockIdx.y * 32;

    const float* __restrict__ h1n = g_h1[par ^ 1];
    const float* __restrict__ h2p = g_h2[par];
    float* __restrict__ h2n = g_h2[par ^ 1];

    const int wk = tid >> 4;
    const int wc4 = tid & 15;
    const int an = tid >> 3;          // 0..31
    const int ak = tid & 7;           // k offsets ak + 8j, j=0..3

    float acc[4][2];
#pragma unroll
    for (int i = 0; i < 4; i++) { acc[i][0] = 0.f; acc[i][1] = 0.f; }

    float4 wreg0, wreg1;
    float areg[4];

    {
        const int k0 = 0;
        wreg0 = *(const float4*)&g_W2T[(size_t)(k0 + wk) * R2 + rb + wc4 * 4];
        wreg1 = *(const float4*)&g_W2T[(size_t)(k0 + wk + 16) * R2 + rb + wc4 * 4];
        const float* abase = h1n + (size_t)(nb + an) * HH + (k0 + ak);
#pragma unroll
        for (int j = 0; j < 4; j++) areg[j] = abase[8 * j];
        *(float4*)&Ws[0][wk][wc4 * 4]      = wreg0;
        *(float4*)&Ws[0][wk + 16][wc4 * 4] = wreg1;
#pragma unroll
        for (int j = 0; j < 4; j++) As[0][ak + 8 * j][an] = areg[j];
    }
    __syncthreads();

#pragma unroll 1
    for (int c = 0; c < L2_NC; c++) {
        if (c + 1 < L2_NC) {
            const int k0 = (c + 1) * 32;
            wreg0 = *(const float4*)&g_W2T[(size_t)(k0 + wk) * R2 + rb + wc4 * 4];
            wreg1 = *(const float4*)&g_W2T[(size_t)(k0 + wk + 16) * R2 + rb + wc4 * 4];
            const float* abase = (k0 < 512)
                ? h1n + (size_t)(nb + an) * HH  + (k0 + ak)
                : h2p + (size_t)(nb + an) * KSZ + (k0 - 512 + ak);
#pragma unroll
            for (int j = 0; j < 4; j++) areg[j] = abase[8 * j];
        }
        const int buf = c & 1;
#pragma unroll
        for (int k = 0; k < 32; k++) {
            float4 w = *(float4*)&Ws[buf][k][tx * 4];
            float2 a = *(float2*)&As[buf][k][ty * 2];
            acc[0][0] = fmaf(w.x, a.x, acc[0][0]); acc[0][1] = fmaf(w.x, a.y, acc[0][1]);
            acc[1][0] = fmaf(w.y, a.x, acc[1][0]); acc[1][1] = fmaf(w.y, a.y, acc[1][1]);
            acc[2][0] = fmaf(w.z, a.x, acc[2][0]); acc[2][1] = fmaf(w.z, a.y, acc[2][1]);
            acc[3][0] = fmaf(w.w, a.x, acc[3][0]); acc[3][1] = fmaf(w.w, a.y, acc[3][1]);
        }
        if (c + 1 < L2_NC) {
            const int nbuf = buf ^ 1;
            *(float4*)&Ws[nbuf][wk][wc4 * 4]      = wreg0;
            *(float4*)&Ws[nbuf][wk + 16][wc4 * 4] = wreg1;
#pragma unroll
            for (int j = 0; j < 4; j++) As[nbuf][ak + 8 * j][an] = areg[j];
            __syncthreads();
        }
    }

    const int h = (rb >> 2) + tx;
    const int r4 = rb + tx * 4;
    const float bi = g_b2p[r4 + 0];
    const float bf = g_b2p[r4 + 1];
    const float bg = g_b2p[r4 + 2];
    const float bo = g_b2p[r4 + 3];
#pragma unroll
    for (int j = 0; j < 2; j++) {
        int n = nb + ty * 2 + j;
        float gi = acc[0][j] + bi;
        float gf = acc[1][j] + bf;
        float gg = acc[2][j] + bg;
        float go = acc[3][j] + bo;
        float c = sigmoidf_(gf) * g_c2[n * KSZ + h] + sigmoidf_(gi) * tanhf(gg);
        g_c2[n * KSZ + h] = c;
        h2n[n * KSZ + h] = sigmoidf_(go) * tanhf(c);
    }
}

// ---------------------------------------------------------------------------
// Attention + output projection, fp32 K/V, high-MLP.  (unchanged from R5)
// One block per batch row (length-sorted order), 512 threads / 16 warps.
// ---------------------------------------------------------------------------
__global__ __launch_bounds__(512) void attn_kernel(const float* __restrict__ enc_key,
                                                   const float* __restrict__ enc_values,
                                                   const float* __restrict__ W_out,
                                                   const float* __restrict__ b_out,
                                                   float* __restrict__ out,
                                                   int step, int par)
{
    __shared__ float sh_q[KSZ];
    __shared__ float sh_c[VSZ];
    __shared__ float sh_e[TT];
    __shared__ float sh_red[16];
    __shared__ float sh_inv;
    __shared__ float sh_acc[16][VSZ];

    const int tid = threadIdx.x;
    const int lane = tid & 31;
    const int warp = tid >> 5;
    const int n = g_order[blockIdx.x];
    const int nv = g_nv[n];

    if (tid < KSZ) sh_q[tid] = g_h2[par ^ 1][n * KSZ + tid];
    __syncthreads();

    float qr[8];
#pragma unroll
    for (int i = 0; i < 8; i++) qr[i] = sh_q[lane * 8 + i];

    // ---- energies ----
    const float* __restrict__ Kb = enc_key + (size_t)n * TT * KSZ;
    float lmax = -1e30f;
    for (int c = 0; c < nv; c += 64) {
        float4 ka[4], kb[4];
        bool act[4];
#pragma unroll
        for (int u = 0; u < 4; u++) {
            int t = c + warp + 16 * u;
            act[u] = (t < nv);
            if (act[u]) {
                const float* kr = Kb + (size_t)t * KSZ + lane * 8;
                ka[u] = *(const float4*)kr;
                kb[u] = *(const float4*)(kr + 4);
            }
        }
#pragma unroll
        for (int u = 0; u < 4; u++) {
            if (act[u]) {
                float s = qr[0] * ka[u].x + qr[1] * ka[u].y + qr[2] * ka[u].z + qr[3] * ka[u].w
                        + qr[4] * kb[u].x + qr[5] * kb[u].y + qr[6] * kb[u].z + qr[7] * kb[u].w;
#pragma unroll
                for (int o = 16; o; o >>= 1) s += __shfl_xor_sync(0xffffffffu, s, o);
                if (lane == 0) sh_e[c + warp + 16 * u] = s;
                lmax = fmaxf(lmax, s);
            }
        }
    }
    if (lane == 0) sh_red[warp] = lmax;
    __syncthreads();

    float emax = sh_red[0];
#pragma unroll
    for (int w = 1; w < 16; w++) emax = fmaxf(emax, sh_red[w]);

    float lsum = 0.f;
    for (int t = tid; t < nv; t += 512) {
        float e = expf(sh_e[t] - emax);
        sh_e[t] = e;
        lsum += e;
    }
#pragma unroll
    for (int o = 16; o; o >>= 1) lsum += __shfl_xor_sync(0xffffffffu, lsum, o);
    __syncthreads();
    if (lane == 0) sh_red[warp] = lsum;
    __syncthreads();
    if (tid == 0) {
        float tot = 0.f;
#pragma unroll
        for (int w = 0; w < 16; w++) tot += sh_red[w];
        sh_inv = 1.f / tot;
    }
    __syncthreads();
    const float inv = sh_inv;

    // ---- context ----
    const float* __restrict__ Vb = enc_values + (size_t)n * TT * VSZ;
    float acc[8];
#pragma unroll
    for (int i = 0; i < 8; i++) acc[i] = 0.f;
    for (int c = 0; c < nv; c += 64) {
        float4 va[4], vb[4];
        float ew[4];
        bool act[4];
#pragma unroll
        for (int u = 0; u < 4; u++) {
            int t = c + warp + 16 * u;
            act[u] = (t < nv);
            if (act[u]) {
                const float* vr = Vb + (size_t)t * VSZ + lane * 8;
                va[u] = *(const float4*)vr;
                vb[u] = *(const float4*)(vr + 4);
                ew[u] = sh_e[t];
            }
        }
#pragma unroll
        for (int u = 0; u < 4; u++) {
            if (act[u]) {
                float e = ew[u];
                acc[0] = fmaf(e, va[u].x, acc[0]); acc[1] = fmaf(e, va[u].y, acc[1]);
                acc[2] = fmaf(e, va[u].z, acc[2]); acc[3] = fmaf(e, va[u].w, acc[3]);
                acc[4] = fmaf(e, vb[u].x, acc[4]); acc[5] = fmaf(e, vb[u].y, acc[5]);
                acc[6] = fmaf(e, vb[u].z, acc[6]); acc[7] = fmaf(e, vb[u].w, acc[7]);
            }
        }
    }
#pragma unroll
    for (int i = 0; i < 8; i++) sh_acc[warp][lane * 8 + i] = acc[i];
    __syncthreads();

    if (tid < VSZ) {
        float ctx = 0.f;
#pragma unroll
        for (int w = 0; w < 16; w++) ctx += sh_acc[w][tid];
        ctx *= inv;
        sh_c[tid] = ctx;
        g_ctx[n * VSZ + tid] = ctx;
    }
    __syncthreads();

    // ---- output projection ----
    for (int v = warp; v < VOCAB; v += 16) {
        float s = 0.f;
        const float* __restrict__ wr = W_out + v * (KSZ + VSZ);
#pragma unroll
        for (int i = lane; i < KSZ + VSZ; i += 32) {
            float f = (i < KSZ) ? sh_q[i] : sh_c[i - KSZ];
            s = fmaf(f, wr[i], s);
        }
#pragma unroll
        for (int o = 16; o; o >>= 1) s += __shfl_xor_sync(0xffffffffu, s, o);
        if (lane == 0) out[((size_t)n * MAXLEN + step) * VOCAB + v] = s + b_out[v];
    }
}

// ---------------------------------------------------------------------------
// kernel_launch: init (3 kernels) + 300 x (lstm1, lstm2, attn)
// ---------------------------------------------------------------------------
extern "C" void kernel_launch(void* const* d_in, const int* in_sizes, int n_in,
                              void* d_out, int out_size)
{
    const float* enc_key    = (const float*)d_in[0];
    const float* enc_values = (const float*)d_in[1];
    const int*   text       = (const int*)  d_in[2];
    const int*   lens       = (const int*)  d_in[3];
    const float* emb        = (const float*)d_in[5];
    const float* W_ih1      = (const float*)d_in[6];
    const float* W_hh1      = (const float*)d_in[7];
    const float* b_ih1      = (const float*)d_in[8];
    const float* b_hh1      = (const float*)d_in[9];
    const float* W_ih2      = (const float*)d_in[10];
    const float* W_hh2      = (const float*)d_in[11];
    const float* b_ih2      = (const float*)d_in[12];
    const float* b_hh2      = (const float*)d_in[13];
    const float* W_out      = (const float*)d_in[14];
    const float* b_out      = (const float*)d_in[15];
    float* out = (float*)d_out;

    init_misc<<<1024, 256>>>(W_ih1, W_hh1, W_ih2, W_hh2, b_ih2, b_hh2, lens);
    embB_kernel<<<dim3(VOCAB, 8), 256>>>(emb, W_ih1, b_ih1, b_hh1);
    sort_kernel<<<1, 256>>>();

    for (int t = 0; t < MAXLEN; t++) {
        int par = t & 1;
        lstm1_kernel<<<dim3(32, 4), 256>>>(text, t, par);
        lstm2_kernel<<<dim3(16, 8), 256>>>(par);
        attn_kernel<<<NB, 512>>>(enc_key, enc_values, W_out, b_out, out, t, par);
    }
}